// round 15
// baseline (speedup 1.0000x reference)
#include <cuda_runtime.h>
#include <cuda_bf16.h>
#include <cstdint>

#define KCB   8192
#define DCB   256
#define NROWS 16384
#define OUTN  4194304
#define LOSS_BLOCKS 512

#define TILE_N  256
#define NTILES  32
#define NCHUNKS 128          // 32 tiles * 4 d-chunks of 64
#define CAP     128
#define MARGIN  2.0e-4f
#define FINF    __int_as_float(0x7f800000)

// ---- device scratch (no allocations allowed) ----
__device__ float  g_zz[NROWS];
__device__ float  g_ee[KCB];
__device__ int    g_idx[NROWS];
__device__ double g_part[LOSS_BLOCKS];
__device__ __nv_bfloat16 g_eb[KCB * DCB];     // emb bf16 [k][d]
__device__ __nv_bfloat16 g_zb[NROWS * DCB];   // z   bf16 [n][d]
__device__ float g_zt[NROWS * DCB];           // z fp32 row-major [n][d]
__device__ int   g_cand[NROWS][CAP];
__device__ float g_cv[NROWS][CAP];            // bf16-GEMM score of each candidate
__device__ int   g_cnt[NROWS];

__device__ __forceinline__ uint32_t smem_u32(const void* p) {
    uint32_t a;
    asm("{ .reg .u64 t; cvta.to.shared.u64 t, %1; cvt.u32.u64 %0, t; }"
        : "=r"(a) : "l"(p));
    return a;
}

// ====== fused prep: blocks [0,512) = zzc work, blocks [512,1536) = ee work =====
__global__ __launch_bounds__(256, 4)
void prep_kernel(const float* __restrict__ z, const float* __restrict__ emb) {
    const int t = threadIdx.x;
    if (blockIdx.x < 512) {
        // ---- zz (bit-exact sequential fp32 order per row) + bf16 + fp32 copy
        __shared__ float T[32][257];
        const int n0 = blockIdx.x * 32;
        const int b = n0 >> 10, hw0 = n0 & 1023;
        const float* zb = z + (size_t)b * 262144 + hw0;
#pragma unroll
        for (int it = 0; it < 32; ++it) {
            int d = it * 8 + (t >> 5);
            T[t & 31][d] = zb[(size_t)d * 1024 + (t & 31)];
        }
        __syncthreads();
        if (t < 32) {
            float s = 0.f;
            for (int d = 0; d < DCB; ++d) {
                float v = T[t][d];
                s = __fadd_rn(s, __fmul_rn(v, v));
            }
            g_zz[n0 + t] = s;
        } else {
            for (int u = t - 32; u < 1024; u += 224) {
                int row = u >> 5;
                int d0 = (u & 31) * 8;
                uint32_t pk[4];
#pragma unroll
                for (int q = 0; q < 4; ++q) {
                    __nv_bfloat162 h = __floats2bfloat162_rn(T[row][d0 + 2 * q], T[row][d0 + 2 * q + 1]);
                    pk[q] = *reinterpret_cast<uint32_t*>(&h);
                }
                *reinterpret_cast<uint4*>(g_zb + (size_t)(n0 + row) * DCB + d0) =
                    make_uint4(pk[0], pk[1], pk[2], pk[3]);
                float* zt = g_zt + (size_t)(n0 + row) * DCB + d0;
                *reinterpret_cast<float4*>(zt) =
                    make_float4(T[row][d0], T[row][d0 + 1], T[row][d0 + 2], T[row][d0 + 3]);
                *reinterpret_cast<float4*>(zt + 4) =
                    make_float4(T[row][d0 + 4], T[row][d0 + 5], T[row][d0 + 6], T[row][d0 + 7]);
            }
        }
    } else {
        // ---- ee (bit-exact order) + bf16 convert of emb, warp per row
        int warp = (int)(blockIdx.x - 512) * 8 + (t >> 5);
        int lane = t & 31;
        const float* e = emb + (size_t)warp * DCB;
        float s = 0.f;
#pragma unroll
        for (int j = 0; j < 8; ++j) {
            float v = e[lane + j * 32];
            s = __fadd_rn(s, __fmul_rn(v, v));
        }
#pragma unroll
        for (int o = 16; o; o >>= 1) s = __fadd_rn(s, __shfl_down_sync(0xffffffffu, s, o));
        if (lane == 0) g_ee[warp] = s;
        float4 v0 = *reinterpret_cast<const float4*>(e + lane * 8);
        float4 v1 = *reinterpret_cast<const float4*>(e + lane * 8 + 4);
        __nv_bfloat162 h[4];
        h[0] = __floats2bfloat162_rn(v0.x, v0.y);
        h[1] = __floats2bfloat162_rn(v0.z, v0.w);
        h[2] = __floats2bfloat162_rn(v1.x, v1.y);
        h[3] = __floats2bfloat162_rn(v1.z, v1.w);
        *reinterpret_cast<uint4*>(g_eb + (size_t)warp * DCB + lane * 8) =
            *reinterpret_cast<uint4*>(h);
    }
}

// ==== fused HMMA GEMM + shortlist (256 thr, warp tile 64x64, 4-stage B ring) ===
__global__ __launch_bounds__(256, 1)
void mma_argmin_kernel() {
    extern __shared__ __align__(1024) char dsm[];
    __shared__ float ee_s[TILE_N];
    __shared__ int   s_cnt[128];
    __shared__ float s_lmw[4][128];

    const int tid  = threadIdx.x;
    const int lane = tid & 31;
    const int wid  = tid >> 5;
    const int wm   = wid >> 2;       // 0..1  (m 64-row half)
    const int wn   = wid & 3;        // 0..3  (n 64-col strip)
    const int row0 = blockIdx.x * 128;

    char* As = dsm;                  // 128 m x 512B rows (256 d), swizzled = 64KB
    char* Bb = dsm + 65536;          // 4-stage ring x 32KB (256 n x 128B chunk rows)

    const uint32_t As_u = smem_u32(As);
    const uint32_t Bb_u = smem_u32(Bb);
#pragma unroll
    for (int j = 0; j < 16; ++j) {
        int idx = j * 256 + tid;          // 4096 16B units
        int m = idx >> 5;
        int du = idx & 31;
        uint4 v = *reinterpret_cast<const uint4*>(g_zb + (size_t)(row0 + m) * DCB + du * 8);
        uint32_t off = (uint32_t)(m * 512 + ((du * 16) ^ ((m & 7) << 4)));
        *reinterpret_cast<uint4*>(As + off) = v;
    }
    if (tid < 128) s_cnt[tid] = 0;

    auto issue_chunk = [&](int g) {
        const __nv_bfloat16* src0 = g_eb + (size_t)(g >> 2) * TILE_N * DCB + (g & 3) * 64;
        uint32_t dstb = Bb_u + (uint32_t)((g & 3) * 32768);
#pragma unroll
        for (int j = 0; j < 8; ++j) {
            int idx = j * 256 + tid;
            int n = idx >> 3;
            int du = idx & 7;
            uint64_t src = __cvta_generic_to_global(src0 + (size_t)n * DCB + du * 8);
            uint32_t d = dstb + (uint32_t)(n * 128 + ((du * 16) ^ ((n & 7) << 4)));
            asm volatile("cp.async.cg.shared.global [%0], [%1], 16;\n"
                         :: "r"(d), "l"(src) : "memory");
        }
    };

    float acc[4][8][4];
#pragma unroll
    for (int mi = 0; mi < 4; ++mi)
#pragma unroll
        for (int ni = 0; ni < 8; ++ni)
#pragma unroll
            for (int r = 0; r < 4; ++r) acc[mi][ni][r] = 0.f;
    float lm[8];
#pragma unroll
    for (int i = 0; i < 8; ++i) lm[i] = FINF;

    issue_chunk(0); asm volatile("cp.async.commit_group;" ::: "memory");
    issue_chunk(1); asm volatile("cp.async.commit_group;" ::: "memory");
    issue_chunk(2); asm volatile("cp.async.commit_group;" ::: "memory");

    const int aq = lane >> 3, ar = lane & 7;
    const uint32_t xorr = (uint32_t)(ar << 4);
    uint32_t amb[4], bnb[4];
#pragma unroll
    for (int mi = 0; mi < 4; ++mi)
        amb[mi] = (uint32_t)((wm * 64 + mi * 16 + (aq & 1) * 8 + ar) * 512);
#pragma unroll
    for (int nb = 0; nb < 4; ++nb)
        bnb[nb] = (uint32_t)((wn * 64 + nb * 16 + (aq >> 1) * 8 + ar) * 128);
    const uint32_t akoff = (uint32_t)((aq >> 1) * 16);
    const uint32_t bkoff = (uint32_t)((aq & 1) * 16);

    for (int g = 0; g < NCHUNKS; ++g) {
        asm volatile("cp.async.wait_group 2;" ::: "memory");
        __syncthreads();
        if ((g & 3) == 0) {
            ee_s[tid] = g_ee[(g >> 2) * TILE_N + tid];
            if (g > 0) {
#pragma unroll
                for (int slot = 0; slot < 8; ++slot) {
                    int mi = slot >> 1, h = slot & 1;
                    int rowl = wm * 64 + mi * 16 + (lane >> 2) + h * 8;
                    float m = fminf(fminf(s_lmw[0][rowl], s_lmw[1][rowl]),
                                    fminf(s_lmw[2][rowl], s_lmw[3][rowl]));
                    lm[slot] = fminf(lm[slot], m);
                }
            }
        }
        if (g + 3 < NCHUNKS) issue_chunk(g + 3);
        asm volatile("cp.async.commit_group;" ::: "memory");

        const uint32_t achk = (uint32_t)((g & 3) * 128);
        const uint32_t bbase = Bb_u + (uint32_t)((g & 3) * 32768);

        uint32_t b[2][8][2];
        {
            uint32_t r0, r1, r2, r3;
#pragma unroll
            for (int nb = 0; nb < 4; ++nb) {
                uint32_t bd = bbase + bnb[nb] + (bkoff ^ xorr);
                asm volatile("ldmatrix.sync.aligned.m8n8.x4.shared.b16 {%0,%1,%2,%3}, [%4];"
                    : "=r"(r0), "=r"(r1), "=r"(r2), "=r"(r3) : "r"(bd));
                b[0][2 * nb][0] = r0; b[0][2 * nb][1] = r1;
                b[0][2 * nb + 1][0] = r2; b[0][2 * nb + 1][1] = r3;
            }
        }
#pragma unroll
        for (int ks = 0; ks < 4; ++ks) {
            const int cur = ks & 1;
            uint32_t a[4][4];
#pragma unroll
            for (int mi = 0; mi < 4; ++mi) {
                uint32_t ad = As_u + amb[mi] + ((achk + (uint32_t)(ks * 32) + akoff) ^ xorr);
                asm volatile("ldmatrix.sync.aligned.m8n8.x4.shared.b16 {%0,%1,%2,%3}, [%4];"
                    : "=r"(a[mi][0]), "=r"(a[mi][1]), "=r"(a[mi][2]), "=r"(a[mi][3])
                    : "r"(ad));
            }
            if (ks < 3) {
                uint32_t r0, r1, r2, r3;
#pragma unroll
                for (int nb = 0; nb < 4; ++nb) {
                    uint32_t bd = bbase + bnb[nb] + (((uint32_t)((ks + 1) * 32) + bkoff) ^ xorr);
                    asm volatile("ldmatrix.sync.aligned.m8n8.x4.shared.b16 {%0,%1,%2,%3}, [%4];"
                        : "=r"(r0), "=r"(r1), "=r"(r2), "=r"(r3) : "r"(bd));
                    b[cur ^ 1][2 * nb][0] = r0; b[cur ^ 1][2 * nb][1] = r1;
                    b[cur ^ 1][2 * nb + 1][0] = r2; b[cur ^ 1][2 * nb + 1][1] = r3;
                }
            }
#pragma unroll
            for (int mi = 0; mi < 4; ++mi)
#pragma unroll
                for (int ni = 0; ni < 8; ++ni)
                    asm volatile(
                        "mma.sync.aligned.m16n8k16.row.col.f32.bf16.bf16.f32 "
                        "{%0,%1,%2,%3},{%4,%5,%6,%7},{%8,%9},{%0,%1,%2,%3};"
                        : "+f"(acc[mi][ni][0]), "+f"(acc[mi][ni][1]),
                          "+f"(acc[mi][ni][2]), "+f"(acc[mi][ni][3])
                        : "r"(a[mi][0]), "r"(a[mi][1]), "r"(a[mi][2]), "r"(a[mi][3]),
                          "r"(b[cur][ni][0]), "r"(b[cur][ni][1]));
        }

        if ((g & 3) == 3) {
            const int t = g >> 2;
            const int k0 = t * TILE_N + wn * 64;
            float eer[16];
#pragma unroll
            for (int ni = 0; ni < 8; ++ni)
#pragma unroll
                for (int e = 0; e < 2; ++e)
                    eer[ni * 2 + e] = ee_s[wn * 64 + ni * 8 + (lane & 3) * 2 + e];
#pragma unroll
            for (int mi = 0; mi < 4; ++mi)
#pragma unroll
                for (int h = 0; h < 2; ++h) {
                    const int slot = mi * 2 + h;
                    const int rowl = wm * 64 + mi * 16 + (lane >> 2) + h * 8;
                    float vv[16];
#pragma unroll
                    for (int ni = 0; ni < 8; ++ni)
#pragma unroll
                        for (int e = 0; e < 2; ++e)
                            vv[ni * 2 + e] = fmaf(-2.f, acc[mi][ni][h * 2 + e], eer[ni * 2 + e]);
                    float m16 = vv[0];
#pragma unroll
                    for (int i = 1; i < 16; ++i) m16 = fminf(m16, vv[i]);
                    m16 = fminf(m16, __shfl_xor_sync(0xffffffffu, m16, 1));
                    m16 = fminf(m16, __shfl_xor_sync(0xffffffffu, m16, 2));
                    float nlm = fminf(lm[slot], m16);
                    lm[slot] = nlm;
                    float thr = nlm + MARGIN;
#pragma unroll
                    for (int i = 0; i < 16; ++i) {
                        if (vv[i] <= thr) {
                            int k = k0 + (i >> 1) * 8 + (lane & 3) * 2 + (i & 1);
                            int c = atomicAdd(&s_cnt[rowl], 1);
                            if (c < CAP) {
                                g_cand[row0 + rowl][c] = k;
                                g_cv[row0 + rowl][c] = vv[i];
                            }
                        }
                    }
#pragma unroll
                    for (int ni = 0; ni < 8; ++ni) {
                        acc[mi][ni][h * 2] = 0.f;
                        acc[mi][ni][h * 2 + 1] = 0.f;
                    }
                    if ((lane & 3) == 0) s_lmw[wn][rowl] = lm[slot];
                }
        }
    }

    asm volatile("cp.async.wait_group 0;" ::: "memory");
    __syncthreads();
    if (tid < 128) g_cnt[row0 + tid] = s_cnt[tid];
}

// ====== exact rescore: warp per row, register-cached candidates, one pass =====
__global__ __launch_bounds__(256, 8)
void rescore_kernel(const float* __restrict__ emb) {
    __shared__ float zrow[8][DCB];
    const int wIn = threadIdx.x >> 5;
    const int lane = threadIdx.x & 31;
    const int n = blockIdx.x * 8 + wIn;
    {
        const float4* zt4 = reinterpret_cast<const float4*>(g_zt + (size_t)n * DCB);
        float4 v0 = zt4[lane * 2];
        float4 v1 = zt4[lane * 2 + 1];
        *reinterpret_cast<float4*>(&zrow[wIn][lane * 8]) = v0;
        *reinterpret_cast<float4*>(&zrow[wIn][lane * 8 + 4]) = v1;
    }
    __syncwarp();

    const float zz = g_zz[n];
    const int craw = g_cnt[n];
    const int c = craw > CAP ? -1 : craw;
    float bs = FINF;
    int bk = KCB;
    const float* zr = zrow[wIn];

    if (c < 0) {                       // overflow fallback: full scan
        for (int k = lane; k < KCB; k += 32) {
            const float4* er4 = reinterpret_cast<const float4*>(emb + (size_t)k * DCB);
            float dot = 0.f;
#pragma unroll 8
            for (int q = 0; q < 64; ++q) {
                float4 e4 = __ldg(er4 + q);
                dot = fmaf(zr[4 * q], e4.x, dot);
                dot = fmaf(zr[4 * q + 1], e4.y, dot);
                dot = fmaf(zr[4 * q + 2], e4.z, dot);
                dot = fmaf(zr[4 * q + 3], e4.w, dot);
            }
            float tt = __fadd_rn(zz, g_ee[k]);
            float s = __fadd_rn(tt, __fmul_rn(-2.0f, dot));
            if (s < bs || (s == bs && k < bk)) { bs = s; bk = k; }
        }
    } else {
        // load candidates once into registers (<= 4 per lane at CAP=128)
        int   ck[4];
        float cv[4];
        int myc = 0;
        for (int i = lane; i < c; i += 32) {
            ck[myc] = g_cand[n][i];
            cv[myc] = g_cv[n][i];
            ++myc;
        }
        float vmin = FINF;
#pragma unroll
        for (int j = 0; j < 4; ++j) if (j < myc) vmin = fminf(vmin, cv[j]);
#pragma unroll
        for (int o = 16; o; o >>= 1)
            vmin = fminf(vmin, __shfl_xor_sync(0xffffffffu, vmin, o));
        const float thr = vmin + MARGIN;
#pragma unroll
        for (int j = 0; j < 4; ++j) {
            if (j >= myc || cv[j] > thr) continue;
            int k = ck[j];
            const float4* er4 = reinterpret_cast<const float4*>(emb + (size_t)k * DCB);
            float dot = 0.f;
#pragma unroll 8
            for (int q = 0; q < 64; ++q) {
                float4 e4 = __ldg(er4 + q);
                dot = fmaf(zr[4 * q], e4.x, dot);
                dot = fmaf(zr[4 * q + 1], e4.y, dot);
                dot = fmaf(zr[4 * q + 2], e4.z, dot);
                dot = fmaf(zr[4 * q + 3], e4.w, dot);
            }
            float tt = __fadd_rn(zz, g_ee[k]);
            float s = __fadd_rn(tt, __fmul_rn(-2.0f, dot));
            if (s < bs || (s == bs && k < bk)) { bs = s; bk = k; }
        }
    }
#pragma unroll
    for (int o = 16; o; o >>= 1) {
        float s2 = __shfl_xor_sync(0xffffffffu, bs, o);
        int   k2 = __shfl_xor_sync(0xffffffffu, bk, o);
        if (s2 < bs || (s2 == bs && k2 < bk)) { bs = s2; bk = k2; }
    }
    if (lane == 0) g_idx[n] = bk;
}

// ============ output + loss (512 thr, smem transpose, coalesced both ways) =====
__global__ __launch_bounds__(512, 2)
void out_kernel(const float* __restrict__ z,
                const float* __restrict__ emb,
                float* __restrict__ out) {
    __shared__ float T[32][257];
    __shared__ double sh[512];
    const int t = threadIdx.x;
    const int lane = t & 31;
    const int w = t >> 5;                 // 0..15
    const int n0 = blockIdx.x * 32;
    const int b = n0 >> 10, hw0 = n0 & 1023;

    // gather 32 emb rows, 16 warps x 2 rows
#pragma unroll
    for (int rr = 0; rr < 2; ++rr) {
        int r = w * 2 + rr;
        const float* er = emb + (size_t)g_idx[n0 + r] * DCB;
#pragma unroll
        for (int jj = 0; jj < 2; ++jj) {
            int col = jj * 128 + lane * 4;
            float4 v = *reinterpret_cast<const float4*>(er + col);
            T[r][col] = v.x; T[r][col + 1] = v.y; T[r][col + 2] = v.z; T[r][col + 3] = v.w;
        }
    }
    __syncthreads();

    const size_t gb = (size_t)b * 262144 + hw0;
    double a0 = 0.0, a1 = 0.0;            // two independent chains (fixed order)
#pragma unroll
    for (int it = 0; it < 16; ++it) {
        int d = it * 16 + w;
        size_t ga = gb + (size_t)d * 1024 + lane;
        float e = T[lane][d];
        out[ga] = e;
        float diff = __fadd_rn(e, -z[ga]);
        if (it & 1) a1 += (double)diff * (double)diff;
        else        a0 += (double)diff * (double)diff;
    }
    sh[t] = a0 + a1;
    __syncthreads();
    for (int o = 256; o; o >>= 1) {
        if (t < o) sh[t] += sh[t + o];
        __syncthreads();
    }
    if (t == 0) g_part[blockIdx.x] = sh[0];
}

__global__ void fin_kernel(float* __restrict__ out, int out_size) {
    __shared__ double sh[LOSS_BLOCKS];
    int t = threadIdx.x;
    sh[t] = g_part[t];
    __syncthreads();
    for (int o = LOSS_BLOCKS / 2; o; o >>= 1) {
        if (t < o) sh[t] += sh[t + o];
        __syncthreads();
    }
    if (t == 0 && out_size > OUTN) {
        float m = (float)(sh[0] / (double)OUTN);
        out[OUTN] = __fadd_rn(m, __fmul_rn(0.25f, m));
    }
}

// ================= launch =================
extern "C" void kernel_launch(void* const* d_in, const int* in_sizes, int n_in,
                              void* d_out, int out_size) {
    const float* z   = (const float*)d_in[0];
    const float* emb = (const float*)d_in[1];
    if (n_in >= 2 && in_sizes[0] == KCB * DCB && in_sizes[1] == OUTN) {
        z   = (const float*)d_in[1];
        emb = (const float*)d_in[0];
    }
    float* out = (float*)d_out;

    static const int DSMEM = 65536 + 4 * 32768;   // A resident + 4-stage B ring = 192KB
    cudaFuncSetAttribute(mma_argmin_kernel,
                         cudaFuncAttributeMaxDynamicSharedMemorySize, DSMEM);

    prep_kernel<<<512 + 1024, 256>>>(z, emb);
    mma_argmin_kernel<<<NROWS / 128, 256, DSMEM>>>();
    rescore_kernel<<<NROWS / 8, 256>>>(emb);
    out_kernel<<<NROWS / 32, 512>>>(z, emb, out);
    fin_kernel<<<1, LOSS_BLOCKS>>>(out, out_size);
}

// round 16
// speedup vs baseline: 1.0116x; 1.0116x over previous
#include <cuda_runtime.h>
#include <cuda_bf16.h>
#include <cstdint>

#define KCB   8192
#define DCB   256
#define NROWS 16384
#define OUTN  4194304
#define LOSS_BLOCKS 512

#define TILE_N  256
#define NTILES  32
#define NCHUNKS 128          // 32 tiles * 4 d-chunks of 64
#define CAP     128
#define MARGIN  2.0e-4f
#define FINF    __int_as_float(0x7f800000)

// ---- device scratch (no allocations allowed) ----
__device__ float  g_zz[NROWS];
__device__ float  g_ee[KCB];
__device__ int    g_idx[NROWS];
__device__ double g_part[LOSS_BLOCKS];
__device__ __nv_bfloat16 g_eb[KCB * DCB];     // emb bf16 [k][d]
__device__ __nv_bfloat16 g_zb[NROWS * DCB];   // z   bf16 [n][d]
__device__ float g_zt[NROWS * DCB];           // z fp32 row-major [n][d]
__device__ int   g_cand[NROWS][CAP];
__device__ float g_cv[NROWS][CAP];            // bf16-GEMM score of each candidate
__device__ int   g_cnt[NROWS];

__device__ __forceinline__ uint32_t smem_u32(const void* p) {
    uint32_t a;
    asm("{ .reg .u64 t; cvta.to.shared.u64 t, %1; cvt.u32.u64 %0, t; }"
        : "=r"(a) : "l"(p));
    return a;
}

// ====== fused prep: blocks [0,512) = zz/convert of z, blocks [512,1536) = ee ===
__global__ __launch_bounds__(256, 4)
void prep_kernel(const float* __restrict__ z, const float* __restrict__ emb) {
    const int t = threadIdx.x;
    if (blockIdx.x < 512) {
        // ---- zz (bit-exact sequential fp32 order per row) + bf16 + fp32 copy
        __shared__ float T[32][257];
        const int n0 = blockIdx.x * 32;
        const int b = n0 >> 10, hw0 = n0 & 1023;
        const float* zb = z + (size_t)b * 262144 + hw0;
#pragma unroll
        for (int it = 0; it < 32; ++it) {
            int d = it * 8 + (t >> 5);
            T[t & 31][d] = zb[(size_t)d * 1024 + (t & 31)];
        }
        __syncthreads();
        if (t < 32) {
            float s = 0.f;
            for (int d = 0; d < DCB; ++d) {
                float v = T[t][d];
                s = __fadd_rn(s, __fmul_rn(v, v));
            }
            g_zz[n0 + t] = s;
        } else {
            for (int u = t - 32; u < 1024; u += 224) {
                int row = u >> 5;
                int d0 = (u & 31) * 8;
                uint32_t pk[4];
#pragma unroll
                for (int q = 0; q < 4; ++q) {
                    __nv_bfloat162 h = __floats2bfloat162_rn(T[row][d0 + 2 * q], T[row][d0 + 2 * q + 1]);
                    pk[q] = *reinterpret_cast<uint32_t*>(&h);
                }
                *reinterpret_cast<uint4*>(g_zb + (size_t)(n0 + row) * DCB + d0) =
                    make_uint4(pk[0], pk[1], pk[2], pk[3]);
                float* zt = g_zt + (size_t)(n0 + row) * DCB + d0;
                *reinterpret_cast<float4*>(zt) =
                    make_float4(T[row][d0], T[row][d0 + 1], T[row][d0 + 2], T[row][d0 + 3]);
                *reinterpret_cast<float4*>(zt + 4) =
                    make_float4(T[row][d0 + 4], T[row][d0 + 5], T[row][d0 + 6], T[row][d0 + 7]);
            }
        }
    } else {
        // ---- ee (bit-exact order) + bf16 convert of emb, warp per row
        int warp = (int)(blockIdx.x - 512) * 8 + (t >> 5);
        int lane = t & 31;
        const float* e = emb + (size_t)warp * DCB;
        float s = 0.f;
#pragma unroll
        for (int j = 0; j < 8; ++j) {
            float v = e[lane + j * 32];
            s = __fadd_rn(s, __fmul_rn(v, v));
        }
#pragma unroll
        for (int o = 16; o; o >>= 1) s = __fadd_rn(s, __shfl_down_sync(0xffffffffu, s, o));
        if (lane == 0) g_ee[warp] = s;
        float4 v0 = *reinterpret_cast<const float4*>(e + lane * 8);
        float4 v1 = *reinterpret_cast<const float4*>(e + lane * 8 + 4);
        __nv_bfloat162 h[4];
        h[0] = __floats2bfloat162_rn(v0.x, v0.y);
        h[1] = __floats2bfloat162_rn(v0.z, v0.w);
        h[2] = __floats2bfloat162_rn(v1.x, v1.y);
        h[3] = __floats2bfloat162_rn(v1.z, v1.w);
        *reinterpret_cast<uint4*>(g_eb + (size_t)warp * DCB + lane * 8) =
            *reinterpret_cast<uint4*>(h);
    }
}

// ==== fused HMMA GEMM + shortlist (256 thr, warp tile 64x64, 4-stage B ring) ===
__global__ __launch_bounds__(256, 1)
void mma_argmin_kernel() {
    extern __shared__ __align__(1024) char dsm[];
    __shared__ float ee_s[TILE_N];
    __shared__ int   s_cnt[128];
    __shared__ float s_lmw[4][128];

    const int tid  = threadIdx.x;
    const int lane = tid & 31;
    const int wid  = tid >> 5;
    const int wm   = wid >> 2;       // 0..1  (m 64-row half)
    const int wn   = wid & 3;        // 0..3  (n 64-col strip)
    const int row0 = blockIdx.x * 128;

    char* As = dsm;                  // 128 m x 512B rows (256 d), swizzled = 64KB
    char* Bb = dsm + 65536;          // 4-stage ring x 32KB (256 n x 128B chunk rows)

    const uint32_t As_u = smem_u32(As);
    const uint32_t Bb_u = smem_u32(Bb);
#pragma unroll
    for (int j = 0; j < 16; ++j) {
        int idx = j * 256 + tid;          // 4096 16B units
        int m = idx >> 5;
        int du = idx & 31;
        uint4 v = *reinterpret_cast<const uint4*>(g_zb + (size_t)(row0 + m) * DCB + du * 8);
        uint32_t off = (uint32_t)(m * 512 + ((du * 16) ^ ((m & 7) << 4)));
        *reinterpret_cast<uint4*>(As + off) = v;
    }
    if (tid < 128) s_cnt[tid] = 0;

    auto issue_chunk = [&](int g) {
        const __nv_bfloat16* src0 = g_eb + (size_t)(g >> 2) * TILE_N * DCB + (g & 3) * 64;
        uint32_t dstb = Bb_u + (uint32_t)((g & 3) * 32768);
#pragma unroll
        for (int j = 0; j < 8; ++j) {
            int idx = j * 256 + tid;
            int n = idx >> 3;
            int du = idx & 7;
            uint64_t src = __cvta_generic_to_global(src0 + (size_t)n * DCB + du * 8);
            uint32_t d = dstb + (uint32_t)(n * 128 + ((du * 16) ^ ((n & 7) << 4)));
            asm volatile("cp.async.cg.shared.global [%0], [%1], 16;\n"
                         :: "r"(d), "l"(src) : "memory");
        }
    };

    float acc[4][8][4];
#pragma unroll
    for (int mi = 0; mi < 4; ++mi)
#pragma unroll
        for (int ni = 0; ni < 8; ++ni)
#pragma unroll
            for (int r = 0; r < 4; ++r) acc[mi][ni][r] = 0.f;
    float lm[8];
#pragma unroll
    for (int i = 0; i < 8; ++i) lm[i] = FINF;

    issue_chunk(0); asm volatile("cp.async.commit_group;" ::: "memory");
    issue_chunk(1); asm volatile("cp.async.commit_group;" ::: "memory");
    issue_chunk(2); asm volatile("cp.async.commit_group;" ::: "memory");

    const int aq = lane >> 3, ar = lane & 7;
    const uint32_t xorr = (uint32_t)(ar << 4);
    uint32_t amb[4], bnb[4];
#pragma unroll
    for (int mi = 0; mi < 4; ++mi)
        amb[mi] = (uint32_t)((wm * 64 + mi * 16 + (aq & 1) * 8 + ar) * 512);
#pragma unroll
    for (int nb = 0; nb < 4; ++nb)
        bnb[nb] = (uint32_t)((wn * 64 + nb * 16 + (aq >> 1) * 8 + ar) * 128);
    const uint32_t akoff = (uint32_t)((aq >> 1) * 16);
    const uint32_t bkoff = (uint32_t)((aq & 1) * 16);

    for (int g = 0; g < NCHUNKS; ++g) {
        asm volatile("cp.async.wait_group 2;" ::: "memory");
        __syncthreads();
        if ((g & 3) == 0) {
            ee_s[tid] = g_ee[(g >> 2) * TILE_N + tid];
            if (g > 0) {
#pragma unroll
                for (int slot = 0; slot < 8; ++slot) {
                    int mi = slot >> 1, h = slot & 1;
                    int rowl = wm * 64 + mi * 16 + (lane >> 2) + h * 8;
                    float m = fminf(fminf(s_lmw[0][rowl], s_lmw[1][rowl]),
                                    fminf(s_lmw[2][rowl], s_lmw[3][rowl]));
                    lm[slot] = fminf(lm[slot], m);
                }
            }
        }
        if (g + 3 < NCHUNKS) issue_chunk(g + 3);
        asm volatile("cp.async.commit_group;" ::: "memory");

        const uint32_t achk = (uint32_t)((g & 3) * 128);
        const uint32_t bbase = Bb_u + (uint32_t)((g & 3) * 32768);

        uint32_t b[2][8][2];
        {
            uint32_t r0, r1, r2, r3;
#pragma unroll
            for (int nb = 0; nb < 4; ++nb) {
                uint32_t bd = bbase + bnb[nb] + (bkoff ^ xorr);
                asm volatile("ldmatrix.sync.aligned.m8n8.x4.shared.b16 {%0,%1,%2,%3}, [%4];"
                    : "=r"(r0), "=r"(r1), "=r"(r2), "=r"(r3) : "r"(bd));
                b[0][2 * nb][0] = r0; b[0][2 * nb][1] = r1;
                b[0][2 * nb + 1][0] = r2; b[0][2 * nb + 1][1] = r3;
            }
        }
#pragma unroll
        for (int ks = 0; ks < 4; ++ks) {
            const int cur = ks & 1;
            uint32_t a[4][4];
#pragma unroll
            for (int mi = 0; mi < 4; ++mi) {
                uint32_t ad = As_u + amb[mi] + ((achk + (uint32_t)(ks * 32) + akoff) ^ xorr);
                asm volatile("ldmatrix.sync.aligned.m8n8.x4.shared.b16 {%0,%1,%2,%3}, [%4];"
                    : "=r"(a[mi][0]), "=r"(a[mi][1]), "=r"(a[mi][2]), "=r"(a[mi][3])
                    : "r"(ad));
            }
            if (ks < 3) {
                uint32_t r0, r1, r2, r3;
#pragma unroll
                for (int nb = 0; nb < 4; ++nb) {
                    uint32_t bd = bbase + bnb[nb] + (((uint32_t)((ks + 1) * 32) + bkoff) ^ xorr);
                    asm volatile("ldmatrix.sync.aligned.m8n8.x4.shared.b16 {%0,%1,%2,%3}, [%4];"
                        : "=r"(r0), "=r"(r1), "=r"(r2), "=r"(r3) : "r"(bd));
                    b[cur ^ 1][2 * nb][0] = r0; b[cur ^ 1][2 * nb][1] = r1;
                    b[cur ^ 1][2 * nb + 1][0] = r2; b[cur ^ 1][2 * nb + 1][1] = r3;
                }
            }
#pragma unroll
            for (int mi = 0; mi < 4; ++mi)
#pragma unroll
                for (int ni = 0; ni < 8; ++ni)
                    asm volatile(
                        "mma.sync.aligned.m16n8k16.row.col.f32.bf16.bf16.f32 "
                        "{%0,%1,%2,%3},{%4,%5,%6,%7},{%8,%9},{%0,%1,%2,%3};"
                        : "+f"(acc[mi][ni][0]), "+f"(acc[mi][ni][1]),
                          "+f"(acc[mi][ni][2]), "+f"(acc[mi][ni][3])
                        : "r"(a[mi][0]), "r"(a[mi][1]), "r"(a[mi][2]), "r"(a[mi][3]),
                          "r"(b[cur][ni][0]), "r"(b[cur][ni][1]));
        }

        if ((g & 3) == 3) {
            const int t = g >> 2;
            const int k0 = t * TILE_N + wn * 64;
            float eer[16];
#pragma unroll
            for (int ni = 0; ni < 8; ++ni)
#pragma unroll
                for (int e = 0; e < 2; ++e)
                    eer[ni * 2 + e] = ee_s[wn * 64 + ni * 8 + (lane & 3) * 2 + e];
#pragma unroll
            for (int mi = 0; mi < 4; ++mi)
#pragma unroll
                for (int h = 0; h < 2; ++h) {
                    const int slot = mi * 2 + h;
                    const int rowl = wm * 64 + mi * 16 + (lane >> 2) + h * 8;
                    float vv[16];
#pragma unroll
                    for (int ni = 0; ni < 8; ++ni)
#pragma unroll
                        for (int e = 0; e < 2; ++e)
                            vv[ni * 2 + e] = fmaf(-2.f, acc[mi][ni][h * 2 + e], eer[ni * 2 + e]);
                    float m16 = vv[0];
#pragma unroll
                    for (int i = 1; i < 16; ++i) m16 = fminf(m16, vv[i]);
                    m16 = fminf(m16, __shfl_xor_sync(0xffffffffu, m16, 1));
                    m16 = fminf(m16, __shfl_xor_sync(0xffffffffu, m16, 2));
                    float nlm = fminf(lm[slot], m16);
                    lm[slot] = nlm;
                    float thr = nlm + MARGIN;
#pragma unroll
                    for (int i = 0; i < 16; ++i) {
                        if (vv[i] <= thr) {
                            int k = k0 + (i >> 1) * 8 + (lane & 3) * 2 + (i & 1);
                            int c = atomicAdd(&s_cnt[rowl], 1);
                            if (c < CAP) {
                                g_cand[row0 + rowl][c] = k;
                                g_cv[row0 + rowl][c] = vv[i];
                            }
                        }
                    }
#pragma unroll
                    for (int ni = 0; ni < 8; ++ni) {
                        acc[mi][ni][h * 2] = 0.f;
                        acc[mi][ni][h * 2 + 1] = 0.f;
                    }
                    if ((lane & 3) == 0) s_lmw[wn][rowl] = lm[slot];
                }
        }
    }

    asm volatile("cp.async.wait_group 0;" ::: "memory");
    __syncthreads();
    if (tid < 128) g_cnt[row0 + tid] = s_cnt[tid];
}

// ====== exact rescore: warp per row, score-prefiltered candidates (R14) =======
__global__ __launch_bounds__(256, 6)
void rescore_kernel(const float* __restrict__ emb) {
    __shared__ float zrow[8][DCB];
    const int wIn = threadIdx.x >> 5;
    const int lane = threadIdx.x & 31;
    const int n = blockIdx.x * 8 + wIn;
    {
        const float4* zt4 = reinterpret_cast<const float4*>(g_zt + (size_t)n * DCB);
        float4 v0 = zt4[lane * 2];
        float4 v1 = zt4[lane * 2 + 1];
        *reinterpret_cast<float4*>(&zrow[wIn][lane * 8]) = v0;
        *reinterpret_cast<float4*>(&zrow[wIn][lane * 8 + 4]) = v1;
    }
    __syncwarp();

    const float zz = g_zz[n];
    const int craw = g_cnt[n];
    const int c = craw > CAP ? -1 : craw;
    float bs = FINF;
    int bk = KCB;
    const float* zr = zrow[wIn];

    if (c < 0) {                       // overflow fallback: full scan
        for (int k = lane; k < KCB; k += 32) {
            const float4* er4 = reinterpret_cast<const float4*>(emb + (size_t)k * DCB);
            float dot = 0.f;
#pragma unroll 8
            for (int q = 0; q < 64; ++q) {
                float4 e4 = __ldg(er4 + q);
                dot = fmaf(zr[4 * q], e4.x, dot);
                dot = fmaf(zr[4 * q + 1], e4.y, dot);
                dot = fmaf(zr[4 * q + 2], e4.z, dot);
                dot = fmaf(zr[4 * q + 3], e4.w, dot);
            }
            float tt = __fadd_rn(zz, g_ee[k]);
            float s = __fadd_rn(tt, __fmul_rn(-2.0f, dot));
            if (s < bs || (s == bs && k < bk)) { bs = s; bk = k; }
        }
    } else {
        // pass 1: min of stored bf16-GEMM scores (= global bf16 min of the row)
        float vmin = FINF;
        for (int i = lane; i < c; i += 32) vmin = fminf(vmin, g_cv[n][i]);
#pragma unroll
        for (int o = 16; o; o >>= 1)
            vmin = fminf(vmin, __shfl_xor_sync(0xffffffffu, vmin, o));
        const float thr = vmin + MARGIN;
        // pass 2: exact fp32 chain only on the margin-set
        for (int i = lane; i < c; i += 32) {
            if (g_cv[n][i] > thr) continue;
            int k = g_cand[n][i];
            const float4* er4 = reinterpret_cast<const float4*>(emb + (size_t)k * DCB);
            float dot = 0.f;
#pragma unroll 8
            for (int q = 0; q < 64; ++q) {
                float4 e4 = __ldg(er4 + q);
                dot = fmaf(zr[4 * q], e4.x, dot);
                dot = fmaf(zr[4 * q + 1], e4.y, dot);
                dot = fmaf(zr[4 * q + 2], e4.z, dot);
                dot = fmaf(zr[4 * q + 3], e4.w, dot);
            }
            float tt = __fadd_rn(zz, g_ee[k]);
            float s = __fadd_rn(tt, __fmul_rn(-2.0f, dot));
            if (s < bs || (s == bs && k < bk)) { bs = s; bk = k; }
        }
    }
#pragma unroll
    for (int o = 16; o; o >>= 1) {
        float s2 = __shfl_xor_sync(0xffffffffu, bs, o);
        int   k2 = __shfl_xor_sync(0xffffffffu, bk, o);
        if (s2 < bs || (s2 == bs && k2 < bk)) { bs = s2; bk = k2; }
    }
    if (lane == 0) g_idx[n] = bk;
}

// ======== output + loss (256 thr / R14 layout, occupancy hint raised) =========
__global__ __launch_bounds__(256, 6)
void out_kernel(const float* __restrict__ z,
                const float* __restrict__ emb,
                float* __restrict__ out) {
    __shared__ float T[32][257];
    __shared__ double sh[256];
    const int t = threadIdx.x;
    const int lane = t & 31;
    const int w = t >> 5;
    const int n0 = blockIdx.x * 32;
    const int b = n0 >> 10, hw0 = n0 & 1023;

#pragma unroll
    for (int rr = 0; rr < 4; ++rr) {
        int r = w * 4 + rr;
        const float* er = emb + (size_t)g_idx[n0 + r] * DCB;
#pragma unroll
        for (int jj = 0; jj < 2; ++jj) {
            int col = jj * 128 + lane * 4;
            float4 v = *reinterpret_cast<const float4*>(er + col);
            T[r][col] = v.x; T[r][col + 1] = v.y; T[r][col + 2] = v.z; T[r][col + 3] = v.w;
        }
    }
    __syncthreads();

    const size_t gb = (size_t)b * 262144 + hw0;
    double acc = 0.0;
#pragma unroll
    for (int it = 0; it < 32; ++it) {
        int d = it * 8 + w;
        size_t ga = gb + (size_t)d * 1024 + lane;
        float e = T[lane][d];
        out[ga] = e;
        float diff = __fadd_rn(e, -z[ga]);
        acc += (double)diff * (double)diff;
    }
    sh[t] = acc;
    __syncthreads();
    for (int o = 128; o; o >>= 1) {
        if (t < o) sh[t] += sh[t + o];
        __syncthreads();
    }
    if (t == 0) g_part[blockIdx.x] = sh[0];
}

__global__ void fin_kernel(float* __restrict__ out, int out_size) {
    __shared__ double sh[LOSS_BLOCKS];
    int t = threadIdx.x;
    sh[t] = g_part[t];
    __syncthreads();
    for (int o = LOSS_BLOCKS / 2; o; o >>= 1) {
        if (t < o) sh[t] += sh[t + o];
        __syncthreads();
    }
    if (t == 0 && out_size > OUTN) {
        float m = (float)(sh[0] / (double)OUTN);
        out[OUTN] = __fadd_rn(m, __fmul_rn(0.25f, m));
    }
}

// ================= launch =================
extern "C" void kernel_launch(void* const* d_in, const int* in_sizes, int n_in,
                              void* d_out, int out_size) {
    const float* z   = (const float*)d_in[0];
    const float* emb = (const float*)d_in[1];
    if (n_in >= 2 && in_sizes[0] == KCB * DCB && in_sizes[1] == OUTN) {
        z   = (const float*)d_in[1];
        emb = (const float*)d_in[0];
    }
    float* out = (float*)d_out;

    static const int DSMEM = 65536 + 4 * 32768;   // A resident + 4-stage B ring = 192KB
    cudaFuncSetAttribute(mma_argmin_kernel,
                         cudaFuncAttributeMaxDynamicSharedMemorySize, DSMEM);

    prep_kernel<<<512 + 1024, 256>>>(z, emb);
    mma_argmin_kernel<<<NROWS / 128, 256, DSMEM>>>();
    rescore_kernel<<<NROWS / 8, 256>>>(emb);
    out_kernel<<<NROWS / 32, 256>>>(z, emb, out);
    fin_kernel<<<1, LOSS_BLOCKS>>>(out, out_size);
}